// round 1
// baseline (speedup 1.0000x reference)
#include <cuda_runtime.h>

// Multi-scale morphological closing, [4,8,256,256] fp32 -> [4,8,4,256,256].
// closing_s = erosion_s(dilation_s(x)), each separable h then v,
// SE_s[j] = j^2/(4*t_s), t_s = 4^s, half-width w_s = 4*2^s, weighted by se_coef.
//
// Key facts used:
//  * pad value +-10000 can never win vs. the always-in-window center tap,
//    so clamping the window to the image (via -+1e9 sentinels) is exact.
//  * penalties c*j^2/(4t) are exact in fp32 (power-of-two * small integer),
//    so fmaf(+-c/(4t), j*j, v) is bit-identical to reference's (v -+ c*se[j]).

namespace {
constexpr int IMGS = 32;     // B*C = 4*8
constexpr int H    = 256;
constexpr int W    = 256;
constexpr int NPIX = H * W;            // 65536
constexpr int NTOT = IMGS * NPIX;      // 2097152
}

// ping-pong scratch (8 MB each) — static device arrays, no allocation
__device__ float g_bufA[NTOT];
__device__ float g_bufB[NTOT];

// ---------------------------------------------------------------------------
// Horizontal pass: block = 256 threads = 4 rows x (64 threads x 4 outputs).
// smem row has +-SW sentinel halo so the inner loop is branch-free with
// compile-time j^2 immediates (out-of-window lanes get a huge penalty).
// ---------------------------------------------------------------------------
template<int SW, int SCALE, bool MX>
__global__ void __launch_bounds__(256) hpass_k(
    const float* __restrict__ in,  long in_img_stride,
    float*       __restrict__ out, long out_img_stride,
    const float* __restrict__ sc)
{
    constexpr int ROWS = 4;
    constexpr int PADW = W + 2 * SW;            // multiple of 4 for all SW
    constexpr float BIG = MX ? -1e9f : 1e9f;

    __shared__ __align__(16) float sm[ROWS][PADW];

    const int rb  = blockIdx.x & (H / ROWS - 1);
    const int img = blockIdx.x / (H / ROWS);
    const float* src = in + (long)img * in_img_stride + (long)(rb * ROWS) * W;

    // cooperative load: rows + sentinel halo
    for (int i = threadIdx.x; i < ROWS * PADW; i += 256) {
        const int r = i / PADW;
        const int p = i - r * PADW;
        const int x = p - SW;
        sm[r][p] = ((unsigned)x < (unsigned)W) ? src[r * W + x] : BIG;
    }
    __syncthreads();

    // kc = se_coef / (4 * 4^SCALE), exact power-of-two scaled
    const float kc  = (*sc) * (1.0f / (float)(4u << (2 * SCALE)));
    const float kcs = MX ? -kc : kc;

    const int r    = threadIdx.x >> 6;
    const int lane = threadIdx.x & 63;          // output x0 = 4*lane .. +3
    const float* row = sm[r];

    float acc[4] = {BIG, BIG, BIG, BIG};

    #pragma unroll
    for (int cch = 0; cch < SW / 2 + 1; ++cch) {
        // padded offset 4*lane + 4*cch  <->  x_q = 4*lane - SW + 4*cch (+l)
        const float4 v4 = *reinterpret_cast<const float4*>(row + lane * 4 + cch * 4);
        const float vv[4] = {v4.x, v4.y, v4.z, v4.w};
        #pragma unroll
        for (int l = 0; l < 4; ++l) {
            #pragma unroll
            for (int k = 0; k < 4; ++k) {
                const int j = 4 * cch + l - SW - k;          // compile-time
                const float jj = (j >= -SW && j <= SW) ? (float)(j * j) : 4.0e12f;
                const float cand = fmaf(kcs, jj, vv[l]);
                acc[k] = MX ? fmaxf(acc[k], cand) : fminf(acc[k], cand);
            }
        }
    }

    float* dst = out + (long)img * out_img_stride + (long)(rb * ROWS + r) * W + lane * 4;
    #pragma unroll
    for (int k = 0; k < 4; ++k) dst[k] = acc[k];
}

// ---------------------------------------------------------------------------
// Vertical pass: block = 256 threads spanning full row width (coalesced LDG),
// each thread produces TY consecutive rows of one column. Fully unrolled,
// compile-time j^2 immediates, window clamped to the image (exact).
// ---------------------------------------------------------------------------
template<int SW, int SCALE, bool MX, int TY>
__global__ void __launch_bounds__(256) vpass_k(
    const float* __restrict__ in,  long in_img_stride,
    float*       __restrict__ out, long out_img_stride,
    const float* __restrict__ sc)
{
    constexpr float BIG = MX ? -1e9f : 1e9f;

    const int yb  = blockIdx.x & (H / TY - 1);
    const int img = blockIdx.x / (H / TY);
    const int x   = threadIdx.x;
    const int y0  = yb * TY;
    const float* base = in + (long)img * in_img_stride + x;

    const float kc  = (*sc) * (1.0f / (float)(4u << (2 * SCALE)));
    const float kcs = MX ? -kc : kc;

    float acc[TY];
    #pragma unroll
    for (int k = 0; k < TY; ++k) acc[k] = BIG;

    #pragma unroll
    for (int rr = 0; rr < TY + 2 * SW; ++rr) {
        const int yin = y0 - SW + rr;
        float v = BIG;
        if (yin >= 0 && yin < H) v = base[(long)yin * W];
        #pragma unroll
        for (int k = 0; k < TY; ++k) {
            const int j = rr - SW - k;                       // compile-time
            if (j >= -SW && j <= SW) {
                const float cand = fmaf(kcs, (float)(j * j), v);
                acc[k] = MX ? fmaxf(acc[k], cand) : fminf(acc[k], cand);
            }
        }
    }

    float* dst = out + (long)img * out_img_stride + (long)y0 * W + x;
    #pragma unroll
    for (int k = 0; k < TY; ++k) dst[k * W] = acc[k];
}

// ---------------------------------------------------------------------------
template<int SW, int SCALE>
static void run_scale(const float* in, float* out_scale_base, const float* sc,
                      float* bufA, float* bufB)
{
    constexpr int TY = 8;
    const int hgrid = IMGS * (H / 4);
    const int vgrid = IMGS * (H / TY);

    // dilation h -> v, erosion h -> v
    hpass_k<SW, SCALE, true ><<<hgrid, 256>>>(in,   NPIX, bufA, NPIX, sc);
    vpass_k<SW, SCALE, true, TY><<<vgrid, 256>>>(bufA, NPIX, bufB, NPIX, sc);
    hpass_k<SW, SCALE, false><<<hgrid, 256>>>(bufB, NPIX, bufA, NPIX, sc);
    vpass_k<SW, SCALE, false, TY><<<vgrid, 256>>>(bufA, NPIX,
                                                  out_scale_base, 4L * NPIX, sc);
}

extern "C" void kernel_launch(void* const* d_in, const int* in_sizes, int n_in,
                              void* d_out, int out_size)
{
    const float* in = (const float*)d_in[0];
    const float* sc = (const float*)d_in[1];
    if (n_in >= 2 && in_sizes[0] == 1) {            // defensive: order swap
        in = (const float*)d_in[1];
        sc = (const float*)d_in[0];
    }
    float* out = (float*)d_out;

    float *bufA = nullptr, *bufB = nullptr;
    cudaGetSymbolAddress((void**)&bufA, g_bufA);
    cudaGetSymbolAddress((void**)&bufB, g_bufB);

    // scale s: t = 4^s, half-width w = 4*2^s; out slice base = out + s*NPIX,
    // per-image stride 4*NPIX (layout [B,C,S,H,W])
    run_scale< 4, 0>(in, out + 0L * NPIX, sc, bufA, bufB);
    run_scale< 8, 1>(in, out + 1L * NPIX, sc, bufA, bufB);
    run_scale<16, 2>(in, out + 2L * NPIX, sc, bufA, bufB);
    run_scale<32, 3>(in, out + 3L * NPIX, sc, bufA, bufB);

    (void)out_size;
}